// round 8
// baseline (speedup 1.0000x reference)
#include <cuda_runtime.h>

#define Hd 64
#define Vd 64
#define INNER 24
#define SEQ 32
#define CAP 8
#define NPAIR 15
#define LRc 0.05f
#define B1c 0.9f
#define B2c 0.999f
#define EPSc 1e-8f

#define NW1 (Hd*INNER)             // 1536
#define OFF_B1 NW1                 // 1536
#define OFF_W2 (NW1 + INNER)       // 1560
#define OFF_B2 (OFF_W2 + INNER*Hd) // 3096
#define NPARAM (OFF_B2 + Hd)       // 3160

struct __align__(16) SmemLayout {
    float h[SEQ*Hd];               // 2048 floats
    union {
        float scratch[4096];       // encode-only (4 warps x 1024)
        struct {
            float P[NPARAM];       // params  w1[i*24+j] | b1 | w2[j*64+o] | b2
            float a1[INNER];
            float dz1[INNER];
            float dout[Hd];
            float scores[NPAIR + 1];
            float esc[CAP];
            int   ord[CAP];
            int   toks[SEQ];       // only live before encode (pre-scratch)
        };
    };
};

__device__ __forceinline__ float wredsum(float x) {
    #pragma unroll
    for (int o = 16; o; o >>= 1) x += __shfl_xor_sync(0xffffffffu, x, o);
    return x;
}

// Exact eps-folded Adam, state (m,v) in REGISTERS, param pair in smem.
//   mhat/(sqrt(vhat)+eps) == m/(sqrt(v)+eps*s2) * (inv1*s2),  s2 = sqrt(1-b2^t)
// v==0 guard: v*rsqrt(v) = 0*inf = NaN; fmaxf(NaN, 0) returns 0 (CUDA semantics).
__device__ __forceinline__ void adam2r(float2* __restrict__ P2, int f,
                                       float2& m, float2& v,
                                       float gx, float gy, float negC, float epsT) {
    m.x = fmaf(B1c, m.x, 0.1f * gx);
    m.y = fmaf(B1c, m.y, 0.1f * gy);
    v.x = fmaf(B2c, v.x, 0.001f * gx * gx);
    v.y = fmaf(B2c, v.y, 0.001f * gy * gy);
    float sx = fmaxf(v.x * __frsqrt_rn(v.x), 0.0f);   // sqrt(v), 0-safe
    float sy = fmaxf(v.y * __frsqrt_rn(v.y), 0.0f);
    float2 p = P2[f];
    p.x = fmaf(negC, __fdividef(m.x, sx + epsT), p.x);
    p.y = fmaf(negC, __fdividef(m.y, sy + epsT), p.y);
    P2[f] = p;
}

__global__ void __launch_bounds__(128, 5) ttt_kernel(
    const int*   __restrict__ seqs,
    const float* __restrict__ embed,
    const float* __restrict__ ffw1, const float* __restrict__ ffb1,
    const float* __restrict__ ffw2, const float* __restrict__ ffb2,
    const float* __restrict__ lng,  const float* __restrict__ lnb,
    const float* __restrict__ scw,  const float* __restrict__ scb,
    const float* __restrict__ mw1,  const float* __restrict__ mb1,
    const float* __restrict__ mw2,  const float* __restrict__ mb2,
    const float* __restrict__ outw, const float* __restrict__ outb,
    float* __restrict__ out)
{
    __shared__ SmemLayout s;
    const int tid  = threadIdx.x;
    const int lane = tid & 31;
    const int w    = tid >> 5;
    const int b    = blockIdx.x;

    // ---- tokens + embeddings (float4) ----
    if (tid < SEQ) s.toks[tid] = seqs[b * SEQ + tid];
    __syncthreads();
    {
        const float4* e4 = (const float4*)embed;
        float4* h4 = (float4*)s.h;
        #pragma unroll
        for (int r = 0; r < 4; r++) {
            int idx = tid + 128 * r;          // 0..511
            int t = idx >> 4, c = idx & 15;
            h4[idx] = e4[s.toks[t] * 16 + c];
        }
    }
    __syncthreads();

    // ---- encode: warp w handles tokens {w, w+4, ..., w+28} ----
    {
        // layer 1: lane owns cols [4*lane, 4*lane+4)
        const float4* w1_4 = (const float4*)ffw1;
        float4 bb = ((const float4*)ffb1)[lane];
        float4 acc[8];
        #pragma unroll
        for (int tk = 0; tk < 8; tk++) acc[tk] = bb;
        #pragma unroll 4
        for (int i = 0; i < Hd; i++) {
            float4 wv = w1_4[i * 32 + lane];
            #pragma unroll
            for (int tk = 0; tk < 8; tk++) {
                float ev = s.h[(w + 4 * tk) * Hd + i];
                acc[tk].x = fmaf(ev, wv.x, acc[tk].x);
                acc[tk].y = fmaf(ev, wv.y, acc[tk].y);
                acc[tk].z = fmaf(ev, wv.z, acc[tk].z);
                acc[tk].w = fmaf(ev, wv.w, acc[tk].w);
            }
        }
        float4* sc4 = (float4*)s.scratch;
        #pragma unroll
        for (int tk = 0; tk < 8; tk++) {
            float4 r;
            r.x = fmaxf(acc[tk].x, 0.0f);
            r.y = fmaxf(acc[tk].y, 0.0f);
            r.z = fmaxf(acc[tk].z, 0.0f);
            r.w = fmaxf(acc[tk].w, 0.0f);
            sc4[w * 256 + tk * 32 + lane] = r;
        }
        __syncwarp();

        // layer 2: lane owns cols [2*lane, 2*lane+2)
        const float2* w2_2 = (const float2*)ffw2;
        float2 fb = ((const float2*)ffb2)[lane];
        float2 a2[8];
        #pragma unroll
        for (int tk = 0; tk < 8; tk++) a2[tk] = fb;
        #pragma unroll 4
        for (int i = 0; i < 2 * Hd; i++) {
            float2 wv = w2_2[i * 32 + lane];
            #pragma unroll
            for (int tk = 0; tk < 8; tk++) {
                float hv = s.scratch[w * 1024 + tk * 128 + i];
                a2[tk].x = fmaf(hv, wv.x, a2[tk].x);
                a2[tk].y = fmaf(hv, wv.y, a2[tk].y);
            }
        }

        // residual + layernorm
        float2 g2  = ((const float2*)lng)[lane];
        float2 be2 = ((const float2*)lnb)[lane];
        float2* h2 = (float2*)s.h;
        #pragma unroll
        for (int tk = 0; tk < 8; tk++) {
            int t = w + 4 * tk;
            float2 x = h2[t * 32 + lane];
            x.x += a2[tk].x; x.y += a2[tk].y;
            float mean = wredsum(x.x + x.y) * (1.0f / 64.0f);
            float d0 = x.x - mean, d1 = x.y - mean;
            float var = wredsum(d0 * d0 + d1 * d1) * (1.0f / 64.0f);
            float rs = rsqrtf(var + 1e-5f);
            float2 r;
            r.x = fmaf(d0 * rs, g2.x, be2.x);
            r.y = fmaf(d1 * rs, g2.y, be2.y);
            h2[t * 32 + lane] = r;
        }
    }
    __syncthreads();

    // ---- scores (scratch dead from here; P/a1/... region live) ----
    for (int p = w; p < NPAIR; p += 4) {
        const float* kk = &s.h[(2 * p)     * Hd];
        const float* vv = &s.h[(2 * p + 1) * Hd];
        float acc = kk[lane]      * scw[lane]
                  + kk[lane + 32] * scw[lane + 32]
                  + vv[lane]      * scw[lane + 64]
                  + vv[lane + 32] * scw[lane + 96];
        acc = wredsum(acc);
        if (lane == 0) s.scores[p] = acc + scb[0];
    }
    __syncthreads();

    // ---- evict-min (thread 0) overlapped with P init (all) ----
    if (tid == 0) {
        #pragma unroll
        for (int i = 0; i < CAP; i++) { s.ord[i] = i; s.esc[i] = s.scores[i]; }
        for (int n = CAP; n < NPAIR; n++) {
            int mi = 0; float mv = s.esc[0];
            #pragma unroll
            for (int i = 1; i < CAP; i++) if (s.esc[i] < mv) { mv = s.esc[i]; mi = i; }
            for (int i = mi; i < CAP - 1; i++) { s.ord[i] = s.ord[i+1]; s.esc[i] = s.esc[i+1]; }
            s.ord[CAP-1] = n; s.esc[CAP-1] = s.scores[n];
        }
    }
    {
        float4* P4 = (float4*)s.P;
        for (int q = tid; q < 384; q += 128) P4[q]       = ((const float4*)mw1)[q];
        for (int q = tid; q < 384; q += 128) P4[390 + q] = ((const float4*)mw2)[q];
        if (tid < 6)  P4[384 + tid] = ((const float4*)mb1)[tid];
        if (tid >= 32 && tid < 48) P4[774 + (tid - 32)] = ((const float4*)mb2)[tid - 32];
    }
    __syncthreads();

    // per-thread constant index seeds for the w1 update loop
    const int p0 = 2 * tid;
    const int j0 = p0 % 24;     // even
    const int i0 = p0 / 24;

    // ---- Adam state in registers (same param indices every step) ----
    float2 mW1[6], vW1[6], mW2[6], vW2[6];
    float2 mB = make_float2(0.f, 0.f), vB = make_float2(0.f, 0.f);
    #pragma unroll
    for (int k = 0; k < 6; k++) {
        mW1[k] = make_float2(0.f, 0.f); vW1[k] = make_float2(0.f, 0.f);
        mW2[k] = make_float2(0.f, 0.f); vW2[k] = make_float2(0.f, 0.f);
    }

    // ---- 8 inner Adam steps ----
    float pb1 = 1.0f, pb2 = 1.0f;
    #pragma unroll 1
    for (int st = 0; st < CAP; st++) {
        pb1 *= B1c; pb2 *= B2c;
        float inv1 = __fdividef(1.0f, 1.0f - pb1);
        float s2   = sqrtf(1.0f - pb2);
        float negC = -LRc * inv1 * s2;
        float epsT = EPSc * s2;
        int koff = (s.ord[st] << 1) * Hd;
        int voff = koff + Hd;

        // fwd layer1: 96 threads, 4 lanes per j
        if (tid < 96) {
            const int j  = ((tid >> 5) << 3) + ((tid & 31) >> 2);
            const int sl = tid & 3;
            float acc = 0.0f;
            #pragma unroll
            for (int k = 0; k < 16; k++)
                acc = fmaf(s.h[koff + sl + 4 * k], s.P[(sl + 4 * k) * INNER + j], acc);
            acc += __shfl_xor_sync(0xffffffffu, acc, 1);
            acc += __shfl_xor_sync(0xffffffffu, acc, 2);
            if (sl == 0) s.a1[j] = fmaxf(acc + s.P[OFF_B1 + j], 0.0f);
        }
        __syncthreads();

        // fwd layer2 + output grad: 128 threads, 2 lanes per o
        {
            const int o = tid >> 1, hf = tid & 1;
            const float* Wp = &s.P[OFF_W2 + (hf * 12) * Hd + o];
            const float* ap = &s.a1[hf * 12];
            float acc = 0.0f;
            #pragma unroll
            for (int k = 0; k < 12; k++) acc = fmaf(ap[k], Wp[k * Hd], acc);
            acc += __shfl_xor_sync(0xffffffffu, acc, 1);
            if (hf == 0)
                s.dout[o] = (acc + s.P[OFF_B2 + o] - s.h[voff + o]) * 0.03125f;
        }
        __syncthreads();

        // backward into hidden: 96 threads, rotated conflict-free
        if (tid < 96) {
            const int j  = ((tid >> 5) << 3) + ((tid & 31) >> 2);
            const int sl = tid & 3;
            float acc = 0.0f;
            #pragma unroll
            for (int k = 0; k < 16; k++) {
                int o = sl + 4 * ((j + k) & 15);
                acc = fmaf(s.P[OFF_W2 + j * Hd + o], s.dout[o], acc);
            }
            acc += __shfl_xor_sync(0xffffffffu, acc, 1);
            acc += __shfl_xor_sync(0xffffffffu, acc, 2);
            if (sl == 0) s.dz1[j] = (s.a1[j] > 0.0f) ? acc : 0.0f;
        }
        __syncthreads();

        // parameter updates (float2, Adam state in registers)
        {
            float2* P2 = (float2*)s.P;
            // w1: pairs (i*24+j, i*24+j+1), j even — incremental index
            int i = i0, j = j0;
            #pragma unroll
            for (int k = 0; k < 6; k++) {
                float hk = s.h[koff + i];
                float2 dz = *(const float2*)&s.dz1[j];
                adam2r(P2, tid + 128 * k, mW1[k], vW1[k],
                       hk * dz.x, hk * dz.y, negC, epsT);
                j += 16; i += 10; if (j >= 24) { j -= 24; i += 1; }
            }
            // w2: pairs (j*64+o, j*64+o+1), o even
            #pragma unroll
            for (int k = 0; k < 6; k++) {
                int p = p0 + 256 * k;
                int jj = p >> 6, o = p & 63;
                float av = s.a1[jj];
                float2 dv = *(const float2*)&s.dout[o];
                adam2r(P2, 780 + tid + 128 * k, mW2[k], vW2[k],
                       av * dv.x, av * dv.y, negC, epsT);
            }
            // b1 (tid 0..11), b2 (tid 32..63) in parallel warps
            if (tid < 12) {
                float2 dz = *(const float2*)&s.dz1[2 * tid];
                adam2r(P2, 768 + tid, mB, vB, dz.x, dz.y, negC, epsT);
            }
            if (tid >= 32 && tid < 64) {
                int q = tid - 32;
                float2 dv = *(const float2*)&s.dout[2 * q];
                adam2r(P2, 1548 + q, mB, vB, dv.x, dv.y, negC, epsT);
            }
        }
        __syncthreads();
    }

    // ---- query through finetuned MLP + output head ----
    {
        const int qoff = (SEQ - 2) * Hd;
        if (tid < 96) {
            const int j  = ((tid >> 5) << 3) + ((tid & 31) >> 2);
            const int sl = tid & 3;
            float acc = 0.0f;
            #pragma unroll
            for (int k = 0; k < 16; k++)
                acc = fmaf(s.h[qoff + sl + 4 * k], s.P[(sl + 4 * k) * INNER + j], acc);
            acc += __shfl_xor_sync(0xffffffffu, acc, 1);
            acc += __shfl_xor_sync(0xffffffffu, acc, 2);
            if (sl == 0) s.a1[j] = fmaxf(acc + s.P[OFF_B1 + j], 0.0f);
        }
        __syncthreads();
        {
            const int o = tid >> 1, hf = tid & 1;
            const float* Wp = &s.P[OFF_W2 + (hf * 12) * Hd + o];
            const float* ap = &s.a1[hf * 12];
            float acc = 0.0f;
            #pragma unroll
            for (int k = 0; k < 12; k++) acc = fmaf(ap[k], Wp[k * Hd], acc);
            acc += __shfl_xor_sync(0xffffffffu, acc, 1);
            if (hf == 0) s.dout[o] = acc + s.P[OFF_B2 + o];
        }
        __syncthreads();
        if (tid < Vd) {
            float acc = outb[tid];
            #pragma unroll 8
            for (int o = 0; o < Hd; o++)
                acc = fmaf(s.dout[o], outw[o * Vd + tid], acc);
            out[b * Vd + tid] = acc;
        }
    }
}

extern "C" void kernel_launch(void* const* d_in, const int* in_sizes, int n_in,
                              void* d_out, int out_size) {
    const int*   seqs  = (const int*)  d_in[0];
    const float* embed = (const float*)d_in[1];
    const float* ffw1  = (const float*)d_in[2];
    const float* ffb1  = (const float*)d_in[3];
    const float* ffw2  = (const float*)d_in[4];
    const float* ffb2  = (const float*)d_in[5];
    const float* lng   = (const float*)d_in[6];
    const float* lnb   = (const float*)d_in[7];
    const float* scw   = (const float*)d_in[8];
    const float* scb   = (const float*)d_in[9];
    const float* mw1   = (const float*)d_in[10];
    const float* mb1   = (const float*)d_in[11];
    const float* mw2   = (const float*)d_in[12];
    const float* mb2   = (const float*)d_in[13];
    const float* outw  = (const float*)d_in[14];
    const float* outb  = (const float*)d_in[15];
    float* out = (float*)d_out;

    int B = in_sizes[0] / SEQ;
    ttt_kernel<<<B, 128>>>(seqs, embed, ffw1, ffb1, ffw2, ffb2, lng, lnb,
                           scw, scb, mw1, mb1, mw2, mb2, outw, outb, out);
}

// round 9
// speedup vs baseline: 1.6634x; 1.6634x over previous
#include <cuda_runtime.h>

#define Hd 64
#define Vd 64
#define INNER 24
#define SEQ 32
#define CAP 8
#define NPAIR 15
#define LRc 0.05f
#define B1c 0.9f
#define B2c 0.999f
#define EPSc 1e-8f

#define NW1 (Hd*INNER)             // 1536
#define OFF_B1 NW1                 // 1536
#define OFF_W2 (NW1 + INNER)       // 1560
#define OFF_B2 (OFF_W2 + INNER*Hd) // 3096
#define NPARAM (OFF_B2 + Hd)       // 3160

struct __align__(16) SmemLayout {
    float h[SEQ*Hd];               // 2048 floats
    union {
        float scratch[4096];       // encode-only (4 warps x 1024)
        struct {
            float P[NPARAM];       // params  w1[i*24+j] | b1 | w2[j*64+o] | b2
            float a1[INNER];       // 16B-aligned (P is 12640B)
            float dz1[INNER];
            float dout[Hd];
            float scores[NPAIR + 1];
            float esc[CAP];
            int   ord[CAP];
            int   toks[SEQ];       // only live before encode (pre-scratch)
        };
    };
};

__device__ __forceinline__ float wredsum(float x) {
    #pragma unroll
    for (int o = 16; o; o >>= 1) x += __shfl_xor_sync(0xffffffffu, x, o);
    return x;
}

// Exact eps-folded Adam on a float4, state (m,v) in REGISTERS, params in smem.
//   mhat/(sqrt(vhat)+eps) == m/(sqrt(v)+eps*s2) * (inv1*s2),  s2 = sqrt(1-b2^t)
// v==0 guard: v*rsqrt(v) = 0*inf = NaN; fmaxf(NaN, 0) returns 0 (CUDA semantics).
__device__ __forceinline__ void adam4r(float4* __restrict__ P4, int f,
                                       float4& m, float4& v, float4 g,
                                       float negC, float epsT) {
    m.x = fmaf(B1c, m.x, 0.1f * g.x);
    m.y = fmaf(B1c, m.y, 0.1f * g.y);
    m.z = fmaf(B1c, m.z, 0.1f * g.z);
    m.w = fmaf(B1c, m.w, 0.1f * g.w);
    v.x = fmaf(B2c, v.x, 0.001f * g.x * g.x);
    v.y = fmaf(B2c, v.y, 0.001f * g.y * g.y);
    v.z = fmaf(B2c, v.z, 0.001f * g.z * g.z);
    v.w = fmaf(B2c, v.w, 0.001f * g.w * g.w);
    float sx = fmaxf(v.x * __frsqrt_rn(v.x), 0.0f);
    float sy = fmaxf(v.y * __frsqrt_rn(v.y), 0.0f);
    float sz = fmaxf(v.z * __frsqrt_rn(v.z), 0.0f);
    float sw = fmaxf(v.w * __frsqrt_rn(v.w), 0.0f);
    float4 p = P4[f];
    p.x = fmaf(negC, __fdividef(m.x, sx + epsT), p.x);
    p.y = fmaf(negC, __fdividef(m.y, sy + epsT), p.y);
    p.z = fmaf(negC, __fdividef(m.z, sz + epsT), p.z);
    p.w = fmaf(negC, __fdividef(m.w, sw + epsT), p.w);
    P4[f] = p;
}

__global__ void __launch_bounds__(128, 4) ttt_kernel(
    const int*   __restrict__ seqs,
    const float* __restrict__ embed,
    const float* __restrict__ ffw1, const float* __restrict__ ffb1,
    const float* __restrict__ ffw2, const float* __restrict__ ffb2,
    const float* __restrict__ lng,  const float* __restrict__ lnb,
    const float* __restrict__ scw,  const float* __restrict__ scb,
    const float* __restrict__ mw1,  const float* __restrict__ mb1,
    const float* __restrict__ mw2,  const float* __restrict__ mb2,
    const float* __restrict__ outw, const float* __restrict__ outb,
    float* __restrict__ out)
{
    __shared__ SmemLayout s;
    const int tid  = threadIdx.x;
    const int lane = tid & 31;
    const int w    = tid >> 5;
    const int b    = blockIdx.x;

    // ---- tokens + embeddings (float4) ----
    if (tid < SEQ) s.toks[tid] = seqs[b * SEQ + tid];
    __syncthreads();
    {
        const float4* e4 = (const float4*)embed;
        float4* h4 = (float4*)s.h;
        #pragma unroll
        for (int r = 0; r < 4; r++) {
            int idx = tid + 128 * r;          // 0..511
            int t = idx >> 4, c = idx & 15;
            h4[idx] = e4[s.toks[t] * 16 + c];
        }
    }
    __syncthreads();

    // ---- encode: warp w handles tokens {w, w+4, ..., w+28} ----
    {
        // layer 1: lane owns cols [4*lane, 4*lane+4)
        const float4* w1_4 = (const float4*)ffw1;
        float4 bb = ((const float4*)ffb1)[lane];
        float4 acc[8];
        #pragma unroll
        for (int tk = 0; tk < 8; tk++) acc[tk] = bb;
        #pragma unroll 4
        for (int i = 0; i < Hd; i++) {
            float4 wv = w1_4[i * 32 + lane];
            #pragma unroll
            for (int tk = 0; tk < 8; tk++) {
                float ev = s.h[(w + 4 * tk) * Hd + i];
                acc[tk].x = fmaf(ev, wv.x, acc[tk].x);
                acc[tk].y = fmaf(ev, wv.y, acc[tk].y);
                acc[tk].z = fmaf(ev, wv.z, acc[tk].z);
                acc[tk].w = fmaf(ev, wv.w, acc[tk].w);
            }
        }
        float4* sc4 = (float4*)s.scratch;
        #pragma unroll
        for (int tk = 0; tk < 8; tk++) {
            float4 r;
            r.x = fmaxf(acc[tk].x, 0.0f);
            r.y = fmaxf(acc[tk].y, 0.0f);
            r.z = fmaxf(acc[tk].z, 0.0f);
            r.w = fmaxf(acc[tk].w, 0.0f);
            sc4[w * 256 + tk * 32 + lane] = r;
        }
        __syncwarp();

        // layer 2: lane owns cols [2*lane, 2*lane+2)
        const float2* w2_2 = (const float2*)ffw2;
        float2 fb = ((const float2*)ffb2)[lane];
        float2 a2[8];
        #pragma unroll
        for (int tk = 0; tk < 8; tk++) a2[tk] = fb;
        #pragma unroll 4
        for (int i = 0; i < 2 * Hd; i++) {
            float2 wv = w2_2[i * 32 + lane];
            #pragma unroll
            for (int tk = 0; tk < 8; tk++) {
                float hv = s.scratch[w * 1024 + tk * 128 + i];
                a2[tk].x = fmaf(hv, wv.x, a2[tk].x);
                a2[tk].y = fmaf(hv, wv.y, a2[tk].y);
            }
        }

        // residual + layernorm
        float2 g2  = ((const float2*)lng)[lane];
        float2 be2 = ((const float2*)lnb)[lane];
        float2* h2 = (float2*)s.h;
        #pragma unroll
        for (int tk = 0; tk < 8; tk++) {
            int t = w + 4 * tk;
            float2 x = h2[t * 32 + lane];
            x.x += a2[tk].x; x.y += a2[tk].y;
            float mean = wredsum(x.x + x.y) * (1.0f / 64.0f);
            float d0 = x.x - mean, d1 = x.y - mean;
            float var = wredsum(d0 * d0 + d1 * d1) * (1.0f / 64.0f);
            float rs = rsqrtf(var + 1e-5f);
            float2 r;
            r.x = fmaf(d0 * rs, g2.x, be2.x);
            r.y = fmaf(d1 * rs, g2.y, be2.y);
            h2[t * 32 + lane] = r;
        }
    }
    __syncthreads();

    // ---- scores (scratch dead from here; P/a1/... region live) ----
    for (int p = w; p < NPAIR; p += 4) {
        const float* kk = &s.h[(2 * p)     * Hd];
        const float* vv = &s.h[(2 * p + 1) * Hd];
        float acc = kk[lane]      * scw[lane]
                  + kk[lane + 32] * scw[lane + 32]
                  + vv[lane]      * scw[lane + 64]
                  + vv[lane + 32] * scw[lane + 96];
        acc = wredsum(acc);
        if (lane == 0) s.scores[p] = acc + scb[0];
    }
    __syncthreads();

    // ---- evict-min (thread 0) overlapped with P init (all) ----
    if (tid == 0) {
        #pragma unroll
        for (int i = 0; i < CAP; i++) { s.ord[i] = i; s.esc[i] = s.scores[i]; }
        for (int n = CAP; n < NPAIR; n++) {
            int mi = 0; float mv = s.esc[0];
            #pragma unroll
            for (int i = 1; i < CAP; i++) if (s.esc[i] < mv) { mv = s.esc[i]; mi = i; }
            for (int i = mi; i < CAP - 1; i++) { s.ord[i] = s.ord[i+1]; s.esc[i] = s.esc[i+1]; }
            s.ord[CAP-1] = n; s.esc[CAP-1] = s.scores[n];
        }
    }
    {
        float4* P4 = (float4*)s.P;
        for (int q = tid; q < 384; q += 128) P4[q]       = ((const float4*)mw1)[q];
        for (int q = tid; q < 384; q += 128) P4[390 + q] = ((const float4*)mw2)[q];
        if (tid < 6)  P4[384 + tid] = ((const float4*)mb1)[tid];
        if (tid >= 32 && tid < 48) P4[774 + (tid - 32)] = ((const float4*)mb2)[tid - 32];
    }
    __syncthreads();

    // per-thread constant index seeds for the w1 float4 update loop
    const int q0 = 4 * tid;
    const int j0 = q0 % 24;     // multiple of 4, row never crossed (24 % 4 == 0)
    const int i0 = q0 / 24;

    // ---- Adam state in registers (same param indices every step) ----
    float4 mW1[3], vW1[3], mW2[3], vW2[3];
    float4 mB = make_float4(0.f,0.f,0.f,0.f), vB = make_float4(0.f,0.f,0.f,0.f);
    #pragma unroll
    for (int k = 0; k < 3; k++) {
        mW1[k] = make_float4(0.f,0.f,0.f,0.f); vW1[k] = make_float4(0.f,0.f,0.f,0.f);
        mW2[k] = make_float4(0.f,0.f,0.f,0.f); vW2[k] = make_float4(0.f,0.f,0.f,0.f);
    }

    // ---- 8 inner Adam steps ----
    float pb1 = 1.0f, pb2 = 1.0f;
    #pragma unroll 1
    for (int st = 0; st < CAP; st++) {
        pb1 *= B1c; pb2 *= B2c;
        float inv1 = __fdividef(1.0f, 1.0f - pb1);
        float s2   = sqrtf(1.0f - pb2);
        float negC = -LRc * inv1 * s2;
        float epsT = EPSc * s2;
        int koff = (s.ord[st] << 1) * Hd;
        int voff = koff + Hd;

        // fwd layer1: 96 threads, 4 lanes per j
        if (tid < 96) {
            const int j  = ((tid >> 5) << 3) + ((tid & 31) >> 2);
            const int sl = tid & 3;
            float acc = 0.0f;
            #pragma unroll
            for (int k = 0; k < 16; k++)
                acc = fmaf(s.h[koff + sl + 4 * k], s.P[(sl + 4 * k) * INNER + j], acc);
            acc += __shfl_xor_sync(0xffffffffu, acc, 1);
            acc += __shfl_xor_sync(0xffffffffu, acc, 2);
            if (sl == 0) s.a1[j] = fmaxf(acc + s.P[OFF_B1 + j], 0.0f);
        }
        __syncthreads();

        // fwd layer2 + output grad: 128 threads, 2 lanes per o
        {
            const int o = tid >> 1, hf = tid & 1;
            const float* Wp = &s.P[OFF_W2 + (hf * 12) * Hd + o];
            const float* ap = &s.a1[hf * 12];
            float acc = 0.0f;
            #pragma unroll
            for (int k = 0; k < 12; k++) acc = fmaf(ap[k], Wp[k * Hd], acc);
            acc += __shfl_xor_sync(0xffffffffu, acc, 1);
            if (hf == 0)
                s.dout[o] = (acc + s.P[OFF_B2 + o] - s.h[voff + o]) * 0.03125f;
        }
        __syncthreads();

        // backward into hidden: 96 threads, rotated conflict-free
        if (tid < 96) {
            const int j  = ((tid >> 5) << 3) + ((tid & 31) >> 2);
            const int sl = tid & 3;
            float acc = 0.0f;
            #pragma unroll
            for (int k = 0; k < 16; k++) {
                int o = sl + 4 * ((j + k) & 15);
                acc = fmaf(s.P[OFF_W2 + j * Hd + o], s.dout[o], acc);
            }
            acc += __shfl_xor_sync(0xffffffffu, acc, 1);
            acc += __shfl_xor_sync(0xffffffffu, acc, 2);
            if (sl == 0) s.dz1[j] = (s.a1[j] > 0.0f) ? acc : 0.0f;
        }
        __syncthreads();

        // parameter updates (float4, Adam state in registers)
        {
            float4* P4 = (float4*)s.P;
            // w1: quad (i*24 + j .. j+3), j multiple of 4 — incremental index
            int i = i0, j = j0;
            #pragma unroll
            for (int k = 0; k < 3; k++) {
                float hk = s.h[koff + i];
                float4 dz = *(const float4*)&s.dz1[j];
                adam4r(P4, tid + 128 * k, mW1[k], vW1[k],
                       make_float4(hk*dz.x, hk*dz.y, hk*dz.z, hk*dz.w), negC, epsT);
                j += 8; i += 21; if (j >= 24) { j -= 24; i += 1; }
            }
            // w2: quad (jj*64 + o .. o+3)
            #pragma unroll
            for (int k = 0; k < 3; k++) {
                int f = tid + 128 * k;
                float av = s.a1[f >> 4];
                float4 dv = ((const float4*)s.dout)[f & 15];
                adam4r(P4, 390 + f, mW2[k], vW2[k],
                       make_float4(av*dv.x, av*dv.y, av*dv.z, av*dv.w), negC, epsT);
            }
            // b1 (threads 0..5), b2 (threads 32..47) in parallel warps
            if (tid < 6) {
                float4 dz = ((const float4*)s.dz1)[tid];
                adam4r(P4, 384 + tid, mB, vB, dz, negC, epsT);
            }
            if (tid >= 32 && tid < 48) {
                float4 dv = ((const float4*)s.dout)[tid - 32];
                adam4r(P4, 774 + (tid - 32), mB, vB, dv, negC, epsT);
            }
        }
        __syncthreads();
    }

    // ---- query through finetuned MLP + output head ----
    {
        const int qoff = (SEQ - 2) * Hd;
        if (tid < 96) {
            const int j  = ((tid >> 5) << 3) + ((tid & 31) >> 2);
            const int sl = tid & 3;
            float acc = 0.0f;
            #pragma unroll
            for (int k = 0; k < 16; k++)
                acc = fmaf(s.h[qoff + sl + 4 * k], s.P[(sl + 4 * k) * INNER + j], acc);
            acc += __shfl_xor_sync(0xffffffffu, acc, 1);
            acc += __shfl_xor_sync(0xffffffffu, acc, 2);
            if (sl == 0) s.a1[j] = fmaxf(acc + s.P[OFF_B1 + j], 0.0f);
        }
        __syncthreads();
        {
            const int o = tid >> 1, hf = tid & 1;
            const float* Wp = &s.P[OFF_W2 + (hf * 12) * Hd + o];
            const float* ap = &s.a1[hf * 12];
            float acc = 0.0f;
            #pragma unroll
            for (int k = 0; k < 12; k++) acc = fmaf(ap[k], Wp[k * Hd], acc);
            acc += __shfl_xor_sync(0xffffffffu, acc, 1);
            if (hf == 0) s.dout[o] = acc + s.P[OFF_B2 + o];
        }
        __syncthreads();
        if (tid < Vd) {
            float acc = outb[tid];
            #pragma unroll 8
            for (int o = 0; o < Hd; o++)
                acc = fmaf(s.dout[o], outw[o * Vd + tid], acc);
            out[b * Vd + tid] = acc;
        }
    }
}

extern "C" void kernel_launch(void* const* d_in, const int* in_sizes, int n_in,
                              void* d_out, int out_size) {
    const int*   seqs  = (const int*)  d_in[0];
    const float* embed = (const float*)d_in[1];
    const float* ffw1  = (const float*)d_in[2];
    const float* ffb1  = (const float*)d_in[3];
    const float* ffw2  = (const float*)d_in[4];
    const float* ffb2  = (const float*)d_in[5];
    const float* lng   = (const float*)d_in[6];
    const float* lnb   = (const float*)d_in[7];
    const float* scw   = (const float*)d_in[8];
    const float* scb   = (const float*)d_in[9];
    const float* mw1   = (const float*)d_in[10];
    const float* mb1   = (const float*)d_in[11];
    const float* mw2   = (const float*)d_in[12];
    const float* mb2   = (const float*)d_in[13];
    const float* outw  = (const float*)d_in[14];
    const float* outb  = (const float*)d_in[15];
    float* out = (float*)d_out;

    int B = in_sizes[0] / SEQ;
    ttt_kernel<<<B, 128>>>(seqs, embed, ffw1, ffb1, ffw2, ffb2, lng, lnb,
                           scw, scb, mw1, mb1, mw2, mb2, outw, outb, out);
}

// round 10
// speedup vs baseline: 1.7072x; 1.0263x over previous
#include <cuda_runtime.h>

#define Hd 64
#define Vd 64
#define INNER 24
#define SEQ 32
#define CAP 8
#define NPAIR 15
#define LRc 0.05f
#define B1c 0.9f
#define B2c 0.999f
#define EPSc 1e-8f

#define NW1 (Hd*INNER)             // 1536
#define OFF_B1 NW1                 // 1536
#define OFF_W2 (NW1 + INNER)       // 1560
#define OFF_B2 (OFF_W2 + INNER*Hd) // 3096
#define NPARAM (OFF_B2 + Hd)       // 3160

struct __align__(16) SmemLayout {
    float h[SEQ*Hd];               // 2048 floats
    union {
        float scratch[4096];       // encode-only (4 warps x 1024)
        struct {
            float P[NPARAM];       // params  w1[i*24+j] | b1 | w2[j*64+o] | b2
            float a1[INNER];       // 16B-aligned (P is 12640B)
            float dz1[INNER];
            float dout[Hd];
            float scores[NPAIR + 1];
            float esc[CAP];
            int   ord[CAP];
            int   toks[SEQ];       // only live before encode (pre-scratch)
        };
    };
};

__device__ __forceinline__ float wredsum(float x) {
    #pragma unroll
    for (int o = 16; o; o >>= 1) x += __shfl_xor_sync(0xffffffffu, x, o);
    return x;
}

// Exact eps-folded Adam on a float4, state (m,v) in REGISTERS, params in smem.
//   mhat/(sqrt(vhat)+eps) == m/(sqrt(v)+eps*s2) * (inv1*s2),  s2 = sqrt(1-b2^t)
// v==0 guard: v*rsqrt(v) = 0*inf = NaN; fmaxf(NaN, 0) returns 0 (CUDA semantics).
__device__ __forceinline__ void adam4r(float4* __restrict__ P4, int f,
                                       float4& m, float4& v, float4 g,
                                       float negC, float epsT) {
    m.x = fmaf(B1c, m.x, 0.1f * g.x);
    m.y = fmaf(B1c, m.y, 0.1f * g.y);
    m.z = fmaf(B1c, m.z, 0.1f * g.z);
    m.w = fmaf(B1c, m.w, 0.1f * g.w);
    v.x = fmaf(B2c, v.x, 0.001f * g.x * g.x);
    v.y = fmaf(B2c, v.y, 0.001f * g.y * g.y);
    v.z = fmaf(B2c, v.z, 0.001f * g.z * g.z);
    v.w = fmaf(B2c, v.w, 0.001f * g.w * g.w);
    float sx = fmaxf(v.x * __frsqrt_rn(v.x), 0.0f);
    float sy = fmaxf(v.y * __frsqrt_rn(v.y), 0.0f);
    float sz = fmaxf(v.z * __frsqrt_rn(v.z), 0.0f);
    float sw = fmaxf(v.w * __frsqrt_rn(v.w), 0.0f);
    float4 p = P4[f];
    p.x = fmaf(negC, __fdividef(m.x, sx + epsT), p.x);
    p.y = fmaf(negC, __fdividef(m.y, sy + epsT), p.y);
    p.z = fmaf(negC, __fdividef(m.z, sz + epsT), p.z);
    p.w = fmaf(negC, __fdividef(m.w, sw + epsT), p.w);
    P4[f] = p;
}

__global__ void __launch_bounds__(128, 4) ttt_kernel(
    const int*   __restrict__ seqs,
    const float* __restrict__ embed,
    const float* __restrict__ ffw1, const float* __restrict__ ffb1,
    const float* __restrict__ ffw2, const float* __restrict__ ffb2,
    const float* __restrict__ lng,  const float* __restrict__ lnb,
    const float* __restrict__ scw,  const float* __restrict__ scb,
    const float* __restrict__ mw1,  const float* __restrict__ mb1,
    const float* __restrict__ mw2,  const float* __restrict__ mb2,
    const float* __restrict__ outw, const float* __restrict__ outb,
    float* __restrict__ out)
{
    __shared__ SmemLayout s;
    const int tid  = threadIdx.x;
    const int lane = tid & 31;
    const int w    = tid >> 5;
    const int b    = blockIdx.x;

    // ---- tokens + embeddings (float4) ----
    if (tid < SEQ) s.toks[tid] = seqs[b * SEQ + tid];
    __syncthreads();
    {
        const float4* e4 = (const float4*)embed;
        float4* h4 = (float4*)s.h;
        #pragma unroll
        for (int r = 0; r < 4; r++) {
            int idx = tid + 128 * r;          // 0..511
            int t = idx >> 4, c = idx & 15;
            h4[idx] = e4[s.toks[t] * 16 + c];
        }
    }
    __syncthreads();

    // ---- encode: warp w handles tokens {w, w+4, ..., w+28} ----
    {
        // layer 1: lane owns cols [4*lane, 4*lane+4); i blocked by 4,
        // activation loads as LDS.128 broadcast (same addr across lanes).
        const float4* w1_4 = (const float4*)ffw1;
        float4 bb = ((const float4*)ffb1)[lane];
        float4 acc[8];
        #pragma unroll
        for (int tk = 0; tk < 8; tk++) acc[tk] = bb;
        #pragma unroll 2
        for (int ib = 0; ib < Hd; ib += 4) {
            float4 wv0 = w1_4[(ib + 0) * 32 + lane];
            float4 wv1 = w1_4[(ib + 1) * 32 + lane];
            float4 wv2 = w1_4[(ib + 2) * 32 + lane];
            float4 wv3 = w1_4[(ib + 3) * 32 + lane];
            #pragma unroll
            for (int tk = 0; tk < 8; tk++) {
                float4 ev = *(const float4*)&s.h[(w + 4 * tk) * Hd + ib];
                acc[tk].x = fmaf(ev.x, wv0.x, acc[tk].x);
                acc[tk].y = fmaf(ev.x, wv0.y, acc[tk].y);
                acc[tk].z = fmaf(ev.x, wv0.z, acc[tk].z);
                acc[tk].w = fmaf(ev.x, wv0.w, acc[tk].w);
                acc[tk].x = fmaf(ev.y, wv1.x, acc[tk].x);
                acc[tk].y = fmaf(ev.y, wv1.y, acc[tk].y);
                acc[tk].z = fmaf(ev.y, wv1.z, acc[tk].z);
                acc[tk].w = fmaf(ev.y, wv1.w, acc[tk].w);
                acc[tk].x = fmaf(ev.z, wv2.x, acc[tk].x);
                acc[tk].y = fmaf(ev.z, wv2.y, acc[tk].y);
                acc[tk].z = fmaf(ev.z, wv2.z, acc[tk].z);
                acc[tk].w = fmaf(ev.z, wv2.w, acc[tk].w);
                acc[tk].x = fmaf(ev.w, wv3.x, acc[tk].x);
                acc[tk].y = fmaf(ev.w, wv3.y, acc[tk].y);
                acc[tk].z = fmaf(ev.w, wv3.z, acc[tk].z);
                acc[tk].w = fmaf(ev.w, wv3.w, acc[tk].w);
            }
        }
        float4* sc4 = (float4*)s.scratch;
        #pragma unroll
        for (int tk = 0; tk < 8; tk++) {
            float4 r;
            r.x = fmaxf(acc[tk].x, 0.0f);
            r.y = fmaxf(acc[tk].y, 0.0f);
            r.z = fmaxf(acc[tk].z, 0.0f);
            r.w = fmaxf(acc[tk].w, 0.0f);
            sc4[w * 256 + tk * 32 + lane] = r;
        }
        __syncwarp();

        // layer 2: lane owns cols [2*lane, 2*lane+2); i blocked by 4
        const float2* w2_2 = (const float2*)ffw2;
        float2 fb = ((const float2*)ffb2)[lane];
        float2 a2[8];
        #pragma unroll
        for (int tk = 0; tk < 8; tk++) a2[tk] = fb;
        #pragma unroll 2
        for (int ib = 0; ib < 2 * Hd; ib += 4) {
            float2 wv0 = w2_2[(ib + 0) * 32 + lane];
            float2 wv1 = w2_2[(ib + 1) * 32 + lane];
            float2 wv2 = w2_2[(ib + 2) * 32 + lane];
            float2 wv3 = w2_2[(ib + 3) * 32 + lane];
            #pragma unroll
            for (int tk = 0; tk < 8; tk++) {
                float4 hv = *(const float4*)&s.scratch[w * 1024 + tk * 128 + ib];
                a2[tk].x = fmaf(hv.x, wv0.x, a2[tk].x);
                a2[tk].y = fmaf(hv.x, wv0.y, a2[tk].y);
                a2[tk].x = fmaf(hv.y, wv1.x, a2[tk].x);
                a2[tk].y = fmaf(hv.y, wv1.y, a2[tk].y);
                a2[tk].x = fmaf(hv.z, wv2.x, a2[tk].x);
                a2[tk].y = fmaf(hv.z, wv2.y, a2[tk].y);
                a2[tk].x = fmaf(hv.w, wv3.x, a2[tk].x);
                a2[tk].y = fmaf(hv.w, wv3.y, a2[tk].y);
            }
        }

        // residual + layernorm
        float2 g2  = ((const float2*)lng)[lane];
        float2 be2 = ((const float2*)lnb)[lane];
        float2* h2 = (float2*)s.h;
        #pragma unroll
        for (int tk = 0; tk < 8; tk++) {
            int t = w + 4 * tk;
            float2 x = h2[t * 32 + lane];
            x.x += a2[tk].x; x.y += a2[tk].y;
            float mean = wredsum(x.x + x.y) * (1.0f / 64.0f);
            float d0 = x.x - mean, d1 = x.y - mean;
            float var = wredsum(d0 * d0 + d1 * d1) * (1.0f / 64.0f);
            float rs = rsqrtf(var + 1e-5f);
            float2 r;
            r.x = fmaf(d0 * rs, g2.x, be2.x);
            r.y = fmaf(d1 * rs, g2.y, be2.y);
            h2[t * 32 + lane] = r;
        }
    }
    __syncthreads();

    // ---- scores (scratch dead from here; P/a1/... region live) ----
    for (int p = w; p < NPAIR; p += 4) {
        const float* kk = &s.h[(2 * p)     * Hd];
        const float* vv = &s.h[(2 * p + 1) * Hd];
        float acc = kk[lane]      * scw[lane]
                  + kk[lane + 32] * scw[lane + 32]
                  + vv[lane]      * scw[lane + 64]
                  + vv[lane + 32] * scw[lane + 96];
        acc = wredsum(acc);
        if (lane == 0) s.scores[p] = acc + scb[0];
    }
    __syncthreads();

    // ---- evict-min (thread 0) overlapped with P init (all) ----
    if (tid == 0) {
        #pragma unroll
        for (int i = 0; i < CAP; i++) { s.ord[i] = i; s.esc[i] = s.scores[i]; }
        for (int n = CAP; n < NPAIR; n++) {
            int mi = 0; float mv = s.esc[0];
            #pragma unroll
            for (int i = 1; i < CAP; i++) if (s.esc[i] < mv) { mv = s.esc[i]; mi = i; }
            for (int i = mi; i < CAP - 1; i++) { s.ord[i] = s.ord[i+1]; s.esc[i] = s.esc[i+1]; }
            s.ord[CAP-1] = n; s.esc[CAP-1] = s.scores[n];
        }
    }
    {
        float4* P4 = (float4*)s.P;
        for (int q = tid; q < 384; q += 128) P4[q]       = ((const float4*)mw1)[q];
        for (int q = tid; q < 384; q += 128) P4[390 + q] = ((const float4*)mw2)[q];
        if (tid < 6)  P4[384 + tid] = ((const float4*)mb1)[tid];
        if (tid >= 32 && tid < 48) P4[774 + (tid - 32)] = ((const float4*)mb2)[tid - 32];
    }
    __syncthreads();

    // per-thread constant index seeds for the w1 float4 update loop
    const int q0 = 4 * tid;
    const int j0 = q0 % 24;     // multiple of 4, row never crossed (24 % 4 == 0)
    const int i0 = q0 / 24;

    // ---- Adam state in registers (same param indices every step) ----
    float4 mW1[3], vW1[3], mW2[3], vW2[3];
    float4 mB = make_float4(0.f,0.f,0.f,0.f), vB = make_float4(0.f,0.f,0.f,0.f);
    #pragma unroll
    for (int k = 0; k < 3; k++) {
        mW1[k] = make_float4(0.f,0.f,0.f,0.f); vW1[k] = make_float4(0.f,0.f,0.f,0.f);
        mW2[k] = make_float4(0.f,0.f,0.f,0.f); vW2[k] = make_float4(0.f,0.f,0.f,0.f);
    }

    // ---- 8 inner Adam steps ----
    float pb1 = 1.0f, pb2 = 1.0f;
    #pragma unroll 1
    for (int st = 0; st < CAP; st++) {
        pb1 *= B1c; pb2 *= B2c;
        float inv1 = __fdividef(1.0f, 1.0f - pb1);
        float s2   = sqrtf(1.0f - pb2);
        float negC = -LRc * inv1 * s2;
        float epsT = EPSc * s2;
        int koff = (s.ord[st] << 1) * Hd;
        int voff = koff + Hd;

        // fwd layer1: 96 threads, 4 lanes per j
        if (tid < 96) {
            const int j  = ((tid >> 5) << 3) + ((tid & 31) >> 2);
            const int sl = tid & 3;
            float acc = 0.0f;
            #pragma unroll
            for (int k = 0; k < 16; k++)
                acc = fmaf(s.h[koff + sl + 4 * k], s.P[(sl + 4 * k) * INNER + j], acc);
            acc += __shfl_xor_sync(0xffffffffu, acc, 1);
            acc += __shfl_xor_sync(0xffffffffu, acc, 2);
            if (sl == 0) s.a1[j] = fmaxf(acc + s.P[OFF_B1 + j], 0.0f);
        }
        __syncthreads();

        // fwd layer2 + output grad: 128 threads, 2 lanes per o
        {
            const int o = tid >> 1, hf = tid & 1;
            const float* Wp = &s.P[OFF_W2 + (hf * 12) * Hd + o];
            const float* ap = &s.a1[hf * 12];
            float acc = 0.0f;
            #pragma unroll
            for (int k = 0; k < 12; k++) acc = fmaf(ap[k], Wp[k * Hd], acc);
            acc += __shfl_xor_sync(0xffffffffu, acc, 1);
            if (hf == 0)
                s.dout[o] = (acc + s.P[OFF_B2 + o] - s.h[voff + o]) * 0.03125f;
        }
        __syncthreads();

        // backward into hidden: 96 threads, rotated conflict-free
        if (tid < 96) {
            const int j  = ((tid >> 5) << 3) + ((tid & 31) >> 2);
            const int sl = tid & 3;
            float acc = 0.0f;
            #pragma unroll
            for (int k = 0; k < 16; k++) {
                int o = sl + 4 * ((j + k) & 15);
                acc = fmaf(s.P[OFF_W2 + j * Hd + o], s.dout[o], acc);
            }
            acc += __shfl_xor_sync(0xffffffffu, acc, 1);
            acc += __shfl_xor_sync(0xffffffffu, acc, 2);
            if (sl == 0) s.dz1[j] = (s.a1[j] > 0.0f) ? acc : 0.0f;
        }
        __syncthreads();

        // parameter updates (float4, Adam state in registers)
        {
            float4* P4 = (float4*)s.P;
            // w1: quad (i*24 + j .. j+3), j multiple of 4 — incremental index
            int i = i0, j = j0;
            #pragma unroll
            for (int k = 0; k < 3; k++) {
                float hk = s.h[koff + i];
                float4 dz = *(const float4*)&s.dz1[j];
                adam4r(P4, tid + 128 * k, mW1[k], vW1[k],
                       make_float4(hk*dz.x, hk*dz.y, hk*dz.z, hk*dz.w), negC, epsT);
                j += 8; i += 21; if (j >= 24) { j -= 24; i += 1; }
            }
            // w2: quad (jj*64 + o .. o+3)
            #pragma unroll
            for (int k = 0; k < 3; k++) {
                int f = tid + 128 * k;
                float av = s.a1[f >> 4];
                float4 dv = ((const float4*)s.dout)[f & 15];
                adam4r(P4, 390 + f, mW2[k], vW2[k],
                       make_float4(av*dv.x, av*dv.y, av*dv.z, av*dv.w), negC, epsT);
            }
            // b1 (threads 0..5), b2 (threads 32..47) in parallel warps
            if (tid < 6) {
                float4 dz = ((const float4*)s.dz1)[tid];
                adam4r(P4, 384 + tid, mB, vB, dz, negC, epsT);
            }
            if (tid >= 32 && tid < 48) {
                float4 dv = ((const float4*)s.dout)[tid - 32];
                adam4r(P4, 774 + (tid - 32), mB, vB, dv, negC, epsT);
            }
        }
        __syncthreads();
    }

    // ---- query through finetuned MLP + output head ----
    {
        const int qoff = (SEQ - 2) * Hd;
        if (tid < 96) {
            const int j  = ((tid >> 5) << 3) + ((tid & 31) >> 2);
            const int sl = tid & 3;
            float acc = 0.0f;
            #pragma unroll
            for (int k = 0; k < 16; k++)
                acc = fmaf(s.h[qoff + sl + 4 * k], s.P[(sl + 4 * k) * INNER + j], acc);
            acc += __shfl_xor_sync(0xffffffffu, acc, 1);
            acc += __shfl_xor_sync(0xffffffffu, acc, 2);
            if (sl == 0) s.a1[j] = fmaxf(acc + s.P[OFF_B1 + j], 0.0f);
        }
        __syncthreads();
        {
            const int o = tid >> 1, hf = tid & 1;
            const float* Wp = &s.P[OFF_W2 + (hf * 12) * Hd + o];
            const float* ap = &s.a1[hf * 12];
            float acc = 0.0f;
            #pragma unroll
            for (int k = 0; k < 12; k++) acc = fmaf(ap[k], Wp[k * Hd], acc);
            acc += __shfl_xor_sync(0xffffffffu, acc, 1);
            if (hf == 0) s.dout[o] = acc + s.P[OFF_B2 + o];
        }
        __syncthreads();
        if (tid < Vd) {
            float acc = outb[tid];
            #pragma unroll 8
            for (int o = 0; o < Hd; o++)
                acc = fmaf(s.dout[o], outw[o * Vd + tid], acc);
            out[b * Vd + tid] = acc;
        }
    }
}

extern "C" void kernel_launch(void* const* d_in, const int* in_sizes, int n_in,
                              void* d_out, int out_size) {
    const int*   seqs  = (const int*)  d_in[0];
    const float* embed = (const float*)d_in[1];
    const float* ffw1  = (const float*)d_in[2];
    const float* ffb1  = (const float*)d_in[3];
    const float* ffw2  = (const float*)d_in[4];
    const float* ffb2  = (const float*)d_in[5];
    const float* lng   = (const float*)d_in[6];
    const float* lnb   = (const float*)d_in[7];
    const float* scw   = (const float*)d_in[8];
    const float* scb   = (const float*)d_in[9];
    const float* mw1   = (const float*)d_in[10];
    const float* mb1   = (const float*)d_in[11];
    const float* mw2   = (const float*)d_in[12];
    const float* mb2   = (const float*)d_in[13];
    const float* outw  = (const float*)d_in[14];
    const float* outb  = (const float*)d_in[15];
    float* out = (float*)d_out;

    int B = in_sizes[0] / SEQ;
    ttt_kernel<<<B, 128>>>(seqs, embed, ffw1, ffb1, ffw2, ffb2, lng, lnb,
                           scw, scb, mw1, mb1, mw2, mb2, outw, outb, out);
}

// round 11
// speedup vs baseline: 1.7515x; 1.0260x over previous
#include <cuda_runtime.h>

#define Hd 64
#define Vd 64
#define INNER 24
#define SEQ 32
#define CAP 8
#define NPAIR 15
#define LRc 0.05f
#define B1c 0.9f
#define B2c 0.999f
#define EPSc 1e-8f

#define NW1 (Hd*INNER)             // 1536
#define OFF_B1 NW1                 // 1536
#define OFF_W2 (NW1 + INNER)       // 1560
#define OFF_B2 (OFF_W2 + INNER*Hd) // 3096
#define NPARAM (OFF_B2 + Hd)       // 3160

typedef unsigned long long ull;

// Packed fp32x2 ops (sm_103a FFMA2 path — per-lane IEEE fp32, bit-identical)
#define PACKF2(d, lo, hi) asm("mov.b64 %0, {%1, %2};" : "=l"(d) : "f"(lo), "f"(hi))
#define UNPACKF2(lo, hi, s) asm("mov.b64 {%0, %1}, %2;" : "=f"(lo), "=f"(hi) : "l"(s))
#define FMAF2(d, a, b, c) asm("fma.rn.f32x2 %0, %1, %2, %3;" : "=l"(d) : "l"(a), "l"(b), "l"(c))
#define MULF2(d, a, b) asm("mul.rn.f32x2 %0, %1, %2;" : "=l"(d) : "l"(a), "l"(b))

struct __align__(16) SmemLayout {
    float h[SEQ*Hd];               // 2048 floats
    union {
        float scratch[4096];       // encode-only (4 warps x 1024)
        struct {
            float P[NPARAM];       // params  w1[i*24+j] | b1 | w2[j*64+o] | b2
            float a1[INNER];       // 16B-aligned (P is 12640B)
            float dz1[INNER];
            float dout[Hd];
            float scores[NPAIR + 1];
            float esc[CAP];
            int   ord[CAP];
            int   toks[SEQ];       // only live before encode (pre-scratch)
        };
    };
};

__device__ __forceinline__ float wredsum(float x) {
    #pragma unroll
    for (int o = 16; o; o >>= 1) x += __shfl_xor_sync(0xffffffffu, x, o);
    return x;
}

// Exact eps-folded Adam on a quad; m/v state PACKED in registers, params in smem.
// Scalar op sequence per component identical to prior rounds:
//   m = fma(B1, m, 0.1*g);  v = fma(B2, v, (0.001*g)*g)
//   s = max(v*rsqrt(v), 0); p += negC * (m / (s + epsT))
__device__ __forceinline__ void adam4p(float4* __restrict__ P4, int f,
                                       ull& mL, ull& mH, ull& vL, ull& vH,
                                       ull gL, ull gH, float negC, float epsT,
                                       ull cB1, ull c01, ull cB2, ull c001) {
    ull t;
    MULF2(t, c01, gL);  FMAF2(mL, cB1, mL, t);
    MULF2(t, c01, gH);  FMAF2(mH, cB1, mH, t);
    MULF2(t, c001, gL); MULF2(t, t, gL); FMAF2(vL, cB2, vL, t);
    MULF2(t, c001, gH); MULF2(t, t, gH); FMAF2(vH, cB2, vH, t);
    float v0, v1, v2, v3, m0, m1, m2, m3;
    UNPACKF2(v0, v1, vL); UNPACKF2(v2, v3, vH);
    UNPACKF2(m0, m1, mL); UNPACKF2(m2, m3, mH);
    float s0 = fmaxf(v0 * __frsqrt_rn(v0), 0.0f);
    float s1 = fmaxf(v1 * __frsqrt_rn(v1), 0.0f);
    float s2_ = fmaxf(v2 * __frsqrt_rn(v2), 0.0f);
    float s3 = fmaxf(v3 * __frsqrt_rn(v3), 0.0f);
    float4 p = P4[f];
    p.x = fmaf(negC, __fdividef(m0, s0 + epsT), p.x);
    p.y = fmaf(negC, __fdividef(m1, s1 + epsT), p.y);
    p.z = fmaf(negC, __fdividef(m2, s2_ + epsT), p.z);
    p.w = fmaf(negC, __fdividef(m3, s3 + epsT), p.w);
    P4[f] = p;
}

__global__ void __launch_bounds__(128, 4) ttt_kernel(
    const int*   __restrict__ seqs,
    const float* __restrict__ embed,
    const float* __restrict__ ffw1, const float* __restrict__ ffb1,
    const float* __restrict__ ffw2, const float* __restrict__ ffb2,
    const float* __restrict__ lng,  const float* __restrict__ lnb,
    const float* __restrict__ scw,  const float* __restrict__ scb,
    const float* __restrict__ mw1,  const float* __restrict__ mb1,
    const float* __restrict__ mw2,  const float* __restrict__ mb2,
    const float* __restrict__ outw, const float* __restrict__ outb,
    float* __restrict__ out)
{
    __shared__ SmemLayout s;
    const int tid  = threadIdx.x;
    const int lane = tid & 31;
    const int w    = tid >> 5;
    const int b    = blockIdx.x;

    // ---- tokens + embeddings (float4) ----
    if (tid < SEQ) s.toks[tid] = seqs[b * SEQ + tid];
    __syncthreads();
    {
        const float4* e4 = (const float4*)embed;
        float4* h4 = (float4*)s.h;
        #pragma unroll
        for (int r = 0; r < 4; r++) {
            int idx = tid + 128 * r;          // 0..511
            int t = idx >> 4, c = idx & 15;
            h4[idx] = e4[s.toks[t] * 16 + c];
        }
    }
    __syncthreads();

    // ---- encode: warp w handles tokens {w, w+4, ..., w+28} ----
    {
        // layer 1 (PACKED f32x2): lane owns cols [4*lane, 4*lane+4) as two
        // packed lane-pairs (x,y)|(z,w); i blocked by 4; activation via
        // LDS.128 broadcast + per-scalar splat.
        const ulonglong2* w1_p = (const ulonglong2*)ffw1;
        ulonglong2 bbp = ((const ulonglong2*)ffb1)[lane];
        ull accL[8], accH[8];
        #pragma unroll
        for (int tk = 0; tk < 8; tk++) { accL[tk] = bbp.x; accH[tk] = bbp.y; }
        #pragma unroll 2
        for (int ib = 0; ib < Hd; ib += 4) {
            ulonglong2 wv0 = w1_p[(ib + 0) * 32 + lane];
            ulonglong2 wv1 = w1_p[(ib + 1) * 32 + lane];
            ulonglong2 wv2 = w1_p[(ib + 2) * 32 + lane];
            ulonglong2 wv3 = w1_p[(ib + 3) * 32 + lane];
            #pragma unroll
            for (int tk = 0; tk < 8; tk++) {
                float4 ev = *(const float4*)&s.h[(w + 4 * tk) * Hd + ib];
                ull e;
                PACKF2(e, ev.x, ev.x);
                FMAF2(accL[tk], e, wv0.x, accL[tk]);
                FMAF2(accH[tk], e, wv0.y, accH[tk]);
                PACKF2(e, ev.y, ev.y);
                FMAF2(accL[tk], e, wv1.x, accL[tk]);
                FMAF2(accH[tk], e, wv1.y, accH[tk]);
                PACKF2(e, ev.z, ev.z);
                FMAF2(accL[tk], e, wv2.x, accL[tk]);
                FMAF2(accH[tk], e, wv2.y, accH[tk]);
                PACKF2(e, ev.w, ev.w);
                FMAF2(accL[tk], e, wv3.x, accL[tk]);
                FMAF2(accH[tk], e, wv3.y, accH[tk]);
            }
        }
        float4* sc4 = (float4*)s.scratch;
        #pragma unroll
        for (int tk = 0; tk < 8; tk++) {
            float a0, a1_, a2_, a3;
            UNPACKF2(a0, a1_, accL[tk]);
            UNPACKF2(a2_, a3, accH[tk]);
            float4 r;
            r.x = fmaxf(a0, 0.0f);
            r.y = fmaxf(a1_, 0.0f);
            r.z = fmaxf(a2_, 0.0f);
            r.w = fmaxf(a3, 0.0f);
            sc4[w * 256 + tk * 32 + lane] = r;
        }
        __syncwarp();

        // layer 2: lane owns cols [2*lane, 2*lane+2); i blocked by 4 (scalar)
        const float2* w2_2 = (const float2*)ffw2;
        float2 fb = ((const float2*)ffb2)[lane];
        float2 a2[8];
        #pragma unroll
        for (int tk = 0; tk < 8; tk++) a2[tk] = fb;
        #pragma unroll 2
        for (int ib = 0; ib < 2 * Hd; ib += 4) {
            float2 wv0 = w2_2[(ib + 0) * 32 + lane];
            float2 wv1 = w2_2[(ib + 1) * 32 + lane];
            float2 wv2 = w2_2[(ib + 2) * 32 + lane];
            float2 wv3 = w2_2[(ib + 3) * 32 + lane];
            #pragma unroll
            for (int tk = 0; tk < 8; tk++) {
                float4 hv = *(const float4*)&s.scratch[w * 1024 + tk * 128 + ib];
                a2[tk].x = fmaf(hv.x, wv0.x, a2[tk].x);
                a2[tk].y = fmaf(hv.x, wv0.y, a2[tk].y);
                a2[tk].x = fmaf(hv.y, wv1.x, a2[tk].x);
                a2[tk].y = fmaf(hv.y, wv1.y, a2[tk].y);
                a2[tk].x = fmaf(hv.z, wv2.x, a2[tk].x);
                a2[tk].y = fmaf(hv.z, wv2.y, a2[tk].y);
                a2[tk].x = fmaf(hv.w, wv3.x, a2[tk].x);
                a2[tk].y = fmaf(hv.w, wv3.y, a2[tk].y);
            }
        }

        // residual + layernorm
        float2 g2  = ((const float2*)lng)[lane];
        float2 be2 = ((const float2*)lnb)[lane];
        float2* h2 = (float2*)s.h;
        #pragma unroll
        for (int tk = 0; tk < 8; tk++) {
            int t = w + 4 * tk;
            float2 x = h2[t * 32 + lane];
            x.x += a2[tk].x; x.y += a2[tk].y;
            float mean = wredsum(x.x + x.y) * (1.0f / 64.0f);
            float d0 = x.x - mean, d1 = x.y - mean;
            float var = wredsum(d0 * d0 + d1 * d1) * (1.0f / 64.0f);
            float rs = rsqrtf(var + 1e-5f);
            float2 r;
            r.x = fmaf(d0 * rs, g2.x, be2.x);
            r.y = fmaf(d1 * rs, g2.y, be2.y);
            h2[t * 32 + lane] = r;
        }
    }
    __syncthreads();

    // ---- scores (scratch dead from here; P/a1/... region live) ----
    for (int p = w; p < NPAIR; p += 4) {
        const float* kk = &s.h[(2 * p)     * Hd];
        const float* vv = &s.h[(2 * p + 1) * Hd];
        float acc = kk[lane]      * scw[lane]
                  + kk[lane + 32] * scw[lane + 32]
                  + vv[lane]      * scw[lane + 64]
                  + vv[lane + 32] * scw[lane + 96];
        acc = wredsum(acc);
        if (lane == 0) s.scores[p] = acc + scb[0];
    }
    __syncthreads();

    // ---- evict-min (thread 0) overlapped with P init (all) ----
    if (tid == 0) {
        #pragma unroll
        for (int i = 0; i < CAP; i++) { s.ord[i] = i; s.esc[i] = s.scores[i]; }
        for (int n = CAP; n < NPAIR; n++) {
            int mi = 0; float mv = s.esc[0];
            #pragma unroll
            for (int i = 1; i < CAP; i++) if (s.esc[i] < mv) { mv = s.esc[i]; mi = i; }
            for (int i = mi; i < CAP - 1; i++) { s.ord[i] = s.ord[i+1]; s.esc[i] = s.esc[i+1]; }
            s.ord[CAP-1] = n; s.esc[CAP-1] = s.scores[n];
        }
    }
    {
        float4* P4 = (float4*)s.P;
        for (int q = tid; q < 384; q += 128) P4[q]       = ((const float4*)mw1)[q];
        for (int q = tid; q < 384; q += 128) P4[390 + q] = ((const float4*)mw2)[q];
        if (tid < 6)  P4[384 + tid] = ((const float4*)mb1)[tid];
        if (tid >= 32 && tid < 48) P4[774 + (tid - 32)] = ((const float4*)mb2)[tid - 32];
    }
    __syncthreads();

    // per-thread constant index seeds for the w1 float4 update loop
    const int q0 = 4 * tid;
    const int j0 = q0 % 24;     // multiple of 4, row never crossed (24 % 4 == 0)
    const int i0 = q0 / 24;

    // packed Adam constants
    ull cB1, c01, cB2, c001;
    PACKF2(cB1, B1c, B1c);
    PACKF2(c01, 0.1f, 0.1f);
    PACKF2(cB2, B2c, B2c);
    PACKF2(c001, 0.001f, 0.001f);

    // ---- Adam state PACKED in registers (same param indices every step) ----
    ull mW1L[3], mW1H[3], vW1L[3], vW1H[3];
    ull mW2L[3], mW2H[3], vW2L[3], vW2H[3];
    ull mBL = 0, mBH = 0, vBL = 0, vBH = 0;
    #pragma unroll
    for (int k = 0; k < 3; k++) {
        mW1L[k] = mW1H[k] = vW1L[k] = vW1H[k] = 0;
        mW2L[k] = mW2H[k] = vW2L[k] = vW2H[k] = 0;
    }

    // ---- 8 inner Adam steps ----
    float pb1 = 1.0f, pb2 = 1.0f;
    #pragma unroll 1
    for (int st = 0; st < CAP; st++) {
        pb1 *= B1c; pb2 *= B2c;
        float inv1 = __fdividef(1.0f, 1.0f - pb1);
        float s2   = sqrtf(1.0f - pb2);
        float negC = -LRc * inv1 * s2;
        float epsT = EPSc * s2;
        int koff = (s.ord[st] << 1) * Hd;
        int voff = koff + Hd;

        // fwd layer1: 96 threads, 4 lanes per j
        if (tid < 96) {
            const int j  = ((tid >> 5) << 3) + ((tid & 31) >> 2);
            const int sl = tid & 3;
            float acc = 0.0f;
            #pragma unroll
            for (int k = 0; k < 16; k++)
                acc = fmaf(s.h[koff + sl + 4 * k], s.P[(sl + 4 * k) * INNER + j], acc);
            acc += __shfl_xor_sync(0xffffffffu, acc, 1);
            acc += __shfl_xor_sync(0xffffffffu, acc, 2);
            if (sl == 0) s.a1[j] = fmaxf(acc + s.P[OFF_B1 + j], 0.0f);
        }
        __syncthreads();

        // fwd layer2 + output grad: 128 threads, 2 lanes per o
        {
            const int o = tid >> 1, hf = tid & 1;
            const float* Wp = &s.P[OFF_W2 + (hf * 12) * Hd + o];
            const float* ap = &s.a1[hf * 12];
            float acc = 0.0f;
            #pragma unroll
            for (int k = 0; k < 12; k++) acc = fmaf(ap[k], Wp[k * Hd], acc);
            acc += __shfl_xor_sync(0xffffffffu, acc, 1);
            if (hf == 0)
                s.dout[o] = (acc + s.P[OFF_B2 + o] - s.h[voff + o]) * 0.03125f;
        }
        __syncthreads();

        // backward into hidden: 96 threads, rotated conflict-free
        if (tid < 96) {
            const int j  = ((tid >> 5) << 3) + ((tid & 31) >> 2);
            const int sl = tid & 3;
            float acc = 0.0f;
            #pragma unroll
            for (int k = 0; k < 16; k++) {
                int o = sl + 4 * ((j + k) & 15);
                acc = fmaf(s.P[OFF_W2 + j * Hd + o], s.dout[o], acc);
            }
            acc += __shfl_xor_sync(0xffffffffu, acc, 1);
            acc += __shfl_xor_sync(0xffffffffu, acc, 2);
            if (sl == 0) s.dz1[j] = (s.a1[j] > 0.0f) ? acc : 0.0f;
        }
        __syncthreads();

        // parameter updates (float4 params, PACKED grads/state)
        {
            float4* P4 = (float4*)s.P;
            // w1: quad (i*24 + j .. j+3), j multiple of 4 — incremental index
            int i = i0, j = j0;
            #pragma unroll
            for (int k = 0; k < 3; k++) {
                float hk = s.h[koff + i];
                ulonglong2 dzp = *(const ulonglong2*)&s.dz1[j];
                ull hk2, gL, gH;
                PACKF2(hk2, hk, hk);
                MULF2(gL, hk2, dzp.x);
                MULF2(gH, hk2, dzp.y);
                adam4p(P4, tid + 128 * k, mW1L[k], mW1H[k], vW1L[k], vW1H[k],
                       gL, gH, negC, epsT, cB1, c01, cB2, c001);
                j += 8; i += 21; if (j >= 24) { j -= 24; i += 1; }
            }
            // w2: quad (jj*64 + o .. o+3)
            #pragma unroll
            for (int k = 0; k < 3; k++) {
                int f = tid + 128 * k;
                float av = s.a1[f >> 4];
                ulonglong2 dvp = ((const ulonglong2*)s.dout)[f & 15];
                ull av2, gL, gH;
                PACKF2(av2, av, av);
                MULF2(gL, av2, dvp.x);
                MULF2(gH, av2, dvp.y);
                adam4p(P4, 390 + f, mW2L[k], mW2H[k], vW2L[k], vW2H[k],
                       gL, gH, negC, epsT, cB1, c01, cB2, c001);
            }
            // b1 (threads 0..5), b2 (threads 32..47) in parallel warps
            if (tid < 6) {
                ulonglong2 dzp = ((const ulonglong2*)s.dz1)[tid];
                adam4p(P4, 384 + tid, mBL, mBH, vBL, vBH,
                       dzp.x, dzp.y, negC, epsT, cB1, c01, cB2, c001);
            }
            if (tid >= 32 && tid < 48) {
                ulonglong2 dvp = ((const ulonglong2*)s.dout)[tid - 32];
                adam4p(P4, 774 + (tid - 32), mBL, mBH, vBL, vBH,
                       dvp.x, dvp.y, negC, epsT, cB1, c01, cB2, c001);
            }
        }
        __syncthreads();
    }

    // ---- query through finetuned MLP + output head ----
    {
        const int qoff = (SEQ - 2) * Hd;
        if (tid < 96) {
            const int j  = ((tid >> 5) << 3) + ((tid & 31) >> 2);
            const int sl = tid & 3;
            float acc = 0.0f;
            #pragma unroll
            for (int k = 0; k < 16; k++)
                acc = fmaf(s.h[qoff + sl + 4 * k], s.P[(sl + 4 * k) * INNER + j], acc);
            acc += __shfl_xor_sync(0xffffffffu, acc, 1);
            acc += __shfl_xor_sync(0xffffffffu, acc, 2);
            if (sl == 0) s.a1[j] = fmaxf(acc + s.P[OFF_B1 + j], 0.0f);
        }
        __syncthreads();
        {
            const int o = tid >> 1, hf = tid & 1;
            const float* Wp = &s.P[OFF_W2 + (hf * 12) * Hd + o];
            const float* ap = &s.a1[hf * 12];
            float acc = 0.0f;
            #pragma unroll
            for (int k = 0; k < 12; k++) acc = fmaf(ap[k], Wp[k * Hd], acc);
            acc += __shfl_xor_sync(0xffffffffu, acc, 1);
            if (hf == 0) s.dout[o] = acc + s.P[OFF_B2 + o];
        }
        __syncthreads();
        if (tid < Vd) {
            float acc = outb[tid];
            #pragma unroll 8
            for (int o = 0; o < Hd; o++)
                acc = fmaf(s.dout[o], outw[o * Vd + tid], acc);
            out[b * Vd + tid] = acc;
        }
    }
}

extern "C" void kernel_launch(void* const* d_in, const int* in_sizes, int n_in,
                              void* d_out, int out_size) {
    const int*   seqs  = (const int*)  d_in[0];
    const float* embed = (const float*)d_in[1];
    const float* ffw1  = (const float*)d_in[2];
    const float* ffb1  = (const float*)d_in[3];
    const float* ffw2  = (const float*)d_in[4];
    const float* ffb2  = (const float*)d_in[5];
    const float* lng   = (const float*)d_in[6];
    const float* lnb   = (const float*)d_in[7];
    const float* scw   = (const float*)d_in[8];
    const float* scb   = (const float*)d_in[9];
    const float* mw1   = (const float*)d_in[10];
    const float* mb1   = (const float*)d_in[11];
    const float* mw2   = (const float*)d_in[12];
    const float* mb2   = (const float*)d_in[13];
    const float* outw  = (const float*)d_in[14];
    const float* outb  = (const float*)d_in[15];
    float* out = (float*)d_out;

    int B = in_sizes[0] / SEQ;
    ttt_kernel<<<B, 128>>>(seqs, embed, ffw1, ffb1, ffw2, ffb2, lng, lnb,
                           scw, scb, mw1, mb1, mw2, mb2, outw, outb, out);
}